// round 14
// baseline (speedup 1.0000x reference)
#include <cuda_runtime.h>
#include <cuda_bf16.h>
#include <math.h>
#include <stdint.h>

#define B_  2
#define L_  4096
#define D_  512
#define H_  8
#define DH_ 64
#define BL_ 8192
#define FF_ 2048

// ---------------- scratch ----------------
__device__ __nv_bfloat16 g_xn [BL_ * D_];
__device__ __nv_bfloat16 g_q [B_ * H_ * L_ * DH_];
__device__ __nv_bfloat16 g_k [B_ * H_ * L_ * DH_];
__device__ __nv_bfloat16 g_v [B_ * H_ * L_ * DH_];
__device__ __nv_bfloat16 g_att[BL_ * D_];
__device__ float g_x1 [BL_ * D_];
__device__ __nv_bfloat16 g_h  [BL_ * D_];
__device__ __nv_bfloat16 g_ff [BL_ * FF_];
__device__ __nv_bfloat16 g_w0 [3 * D_ * D_];
__device__ __nv_bfloat16 g_w1 [D_ * D_];
__device__ __nv_bfloat16 g_w2 [FF_ * D_];
__device__ __nv_bfloat16 g_w3 [D_ * FF_];

__device__ __forceinline__ float exp2fast(float x) {
    float r;
    asm("ex2.approx.f32 %0, %1;" : "=f"(r) : "f"(x));
    return r;
}
__device__ __forceinline__ uint32_t packbf(float lo, float hi) {
    uint32_t r;
    asm("cvt.rn.bf16x2.f32 %0, %1, %2;" : "=r"(r) : "f"(hi), "f"(lo));
    return r;
}

#define MMA_BF16(d, a, b0, b1)                                               \
    asm volatile(                                                            \
        "mma.sync.aligned.m16n8k16.row.col.f32.bf16.bf16.f32 "               \
        "{%0,%1,%2,%3}, {%4,%5,%6,%7}, {%8,%9}, {%0,%1,%2,%3};"              \
        : "+f"(d[0]), "+f"(d[1]), "+f"(d[2]), "+f"(d[3])                     \
        : "r"(a[0]), "r"(a[1]), "r"(a[2]), "r"(a[3]), "r"(b0), "r"(b1))

#define LDSM_X4(r0, r1, r2, r3, addr)                                        \
    asm volatile("ldmatrix.sync.aligned.m8n8.x4.shared.b16 {%0,%1,%2,%3}, [%4];" \
        : "=r"(r0), "=r"(r1), "=r"(r2), "=r"(r3) : "r"(addr))

#define LDSM_X4T(r0, r1, r2, r3, addr)                                       \
    asm volatile("ldmatrix.sync.aligned.m8n8.x4.trans.shared.b16 {%0,%1,%2,%3}, [%4];" \
        : "=r"(r0), "=r"(r1), "=r"(r2), "=r"(r3) : "r"(addr))

// ============ fused prep: weight conversion + LN1 ============
#define NW_BLOCKS ((3 * D_ * D_ + D_ * D_ + FF_ * D_ + D_ * FF_) / 1024)

__global__ __launch_bounds__(256) void prep_kernel(
    const float* __restrict__ s0, __nv_bfloat16* __restrict__ d0,
    const float* __restrict__ s1, __nv_bfloat16* __restrict__ d1,
    const float* __restrict__ s2, __nv_bfloat16* __restrict__ d2,
    const float* __restrict__ s3, __nv_bfloat16* __restrict__ d3,
    const float* __restrict__ x, const float* __restrict__ lg,
    const float* __restrict__ lb, __nv_bfloat16* __restrict__ y)
{
    if (blockIdx.x < NW_BLOCKS) {
        const int n0 = 3 * D_ * D_, n1 = D_ * D_, n2 = FF_ * D_;
        int i = (blockIdx.x * 256 + threadIdx.x) * 4;
        const float* src; __nv_bfloat16* dst; int off;
        if (i < n0)                { src = s0; dst = d0; off = i; }
        else if (i < n0 + n1)      { src = s1; dst = d1; off = i - n0; }
        else if (i < n0 + n1 + n2) { src = s2; dst = d2; off = i - n0 - n1; }
        else                       { src = s3; dst = d3; off = i - n0 - n1 - n2; }
        float4 v = *(const float4*)(src + off);
        uint2 o;
        o.x = packbf(v.x, v.y);
        o.y = packbf(v.z, v.w);
        *(uint2*)(dst + off) = o;
        return;
    }
    int row = blockIdx.x - NW_BLOCKS;
    const float* xr = x + (size_t)row * D_;
    __nv_bfloat16* yr = y + (size_t)row * D_;
    int tid = threadIdx.x;
    float v0 = xr[tid], v1 = xr[tid + 256];
    float s = v0 + v1, ss = v0 * v0 + v1 * v1;
    #pragma unroll
    for (int o = 16; o > 0; o >>= 1) {
        s  += __shfl_xor_sync(0xffffffffu, s,  o);
        ss += __shfl_xor_sync(0xffffffffu, ss, o);
    }
    __shared__ float red[16];
    int w = tid >> 5, lane = tid & 31;
    if (lane == 0) { red[w] = s; red[w + 8] = ss; }
    __syncthreads();
    float S = 0.f, SS = 0.f;
    #pragma unroll
    for (int i = 0; i < 8; i++) { S += red[i]; SS += red[i + 8]; }
    float mu = S * (1.0f / D_);
    float inv = rsqrtf(SS * (1.0f / D_) - mu * mu + 1e-5f);
    yr[tid]       = __float2bfloat16((v0 - mu) * inv * lg[tid]       + lb[tid]);
    yr[tid + 256] = __float2bfloat16((v1 - mu) * inv * lg[tid + 256] + lb[tid + 256]);
}

// ============ LayerNorm (standalone, for LN2) ============
__global__ __launch_bounds__(256) void ln_kernel(const float* __restrict__ x,
                                                 const float* __restrict__ g,
                                                 const float* __restrict__ b,
                                                 __nv_bfloat16* __restrict__ y) {
    int row = blockIdx.x;
    const float* xr = x + (size_t)row * D_;
    __nv_bfloat16* yr = y + (size_t)row * D_;
    int tid = threadIdx.x;
    float v0 = xr[tid], v1 = xr[tid + 256];
    float s = v0 + v1, ss = v0 * v0 + v1 * v1;
    #pragma unroll
    for (int o = 16; o > 0; o >>= 1) {
        s  += __shfl_xor_sync(0xffffffffu, s,  o);
        ss += __shfl_xor_sync(0xffffffffu, ss, o);
    }
    __shared__ float red[16];
    int w = tid >> 5, lane = tid & 31;
    if (lane == 0) { red[w] = s; red[w + 8] = ss; }
    __syncthreads();
    float S = 0.f, SS = 0.f;
    #pragma unroll
    for (int i = 0; i < 8; i++) { S += red[i]; SS += red[i + 8]; }
    float mu = S * (1.0f / D_);
    float inv = rsqrtf(SS * (1.0f / D_) - mu * mu + 1e-5f);
    yr[tid]       = __float2bfloat16((v0 - mu) * inv * g[tid]       + b[tid]);
    yr[tid + 256] = __float2bfloat16((v1 - mu) * inv * g[tid + 256] + b[tid + 256]);
}

// ============ bf16 mma GEMM: 128x64 block, 4(M)x2(N) warps, 32x32 warp tile,
//              4-stage cp.async, 3 CTAs/SM ============
#define ROWG 80
#define STGA_B (128 * ROWG)            // 10240
#define STGW_B (64 * ROWG)             // 5120
#define STAGE_B (STGA_B + STGW_B)      // 15360
#define GEMM_SMEM_B (4 * STAGE_B)      // 61440
#define MODE_QKV   0
#define MODE_RESID 1
#define MODE_SILU  2

__global__ __launch_bounds__(256, 3) void mma_gemm(
    const __nv_bfloat16* __restrict__ A, const __nv_bfloat16* __restrict__ W,
    int K, int N, int mode, const float* __restrict__ resid,
    float* __restrict__ out, __nv_bfloat16* __restrict__ outb,
    __nv_bfloat16* __restrict__ oq, __nv_bfloat16* __restrict__ okk,
    __nv_bfloat16* __restrict__ ov)
{
    extern __shared__ char smg[];
    uint32_t sbase = (uint32_t)__cvta_generic_to_shared(smg);
    int tid = threadIdx.x;
    int wid = tid >> 5, lane = tid & 31;
    int wm = wid & 3, wn = wid >> 2;       // 4 M-strips x 2 N-strips
    int g = lane >> 2, qd = lane & 3;
    int bm = blockIdx.y, bn = blockIdx.x;
    const __nv_bfloat16* Ab = A + (size_t)bm * 128 * K;
    const __nv_bfloat16* Wb = W + (size_t)bn * 64 * K;
    const int NC = K >> 5;

    int arow = wm * 32 + (lane & 7) + ((lane >> 3) & 1) * 8;
    int acol = (lane >> 4) * 16;
    int wrow = wn * 32 + (lane & 7) + ((lane >> 4) & 1) * 8;
    int wcol = ((lane >> 3) & 1) * 16;

    float acc[2][4][4];
    #pragma unroll
    for (int i = 0; i < 2; i++)
        #pragma unroll
        for (int j = 0; j < 4; j++)
            #pragma unroll
            for (int e = 0; e < 4; e++) acc[i][j][e] = 0.f;

    auto load_stage = [&](int c, int st) {
        int k0 = c << 5;
        // A: 128 rows x 32 cols (64B/row) = 512 x 16B
        #pragma unroll
        for (int i = 0; i < 2; i++) {
            int idx = tid + i * 256;
            int r = idx >> 2, cb = idx & 3;
            uint32_t da = sbase + (uint32_t)(st * STAGE_B + r * ROWG + cb * 16);
            asm volatile("cp.async.cg.shared.global [%0], [%1], 16;"
                         :: "r"(da), "l"(Ab + (size_t)r * K + k0 + cb * 8) : "memory");
        }
        // W: 64 rows = 256 x 16B
        {
            int r = tid >> 2, cb = tid & 3;
            uint32_t dw = sbase + (uint32_t)(st * STAGE_B + STGA_B + r * ROWG + cb * 16);
            asm volatile("cp.async.cg.shared.global [%0], [%1], 16;"
                         :: "r"(dw), "l"(Wb + (size_t)r * K + k0 + cb * 8) : "memory");
        }
        asm volatile("cp.async.commit_group;" ::: "memory");
    };

    load_stage(0, 0); load_stage(1, 1); load_stage(2, 2);

    for (int c = 0; c < NC; c++) {
        int rem = NC - 1 - c;
        if (rem >= 2)      asm volatile("cp.async.wait_group 2;" ::: "memory");
        else if (rem == 1) asm volatile("cp.async.wait_group 1;" ::: "memory");
        else               asm volatile("cp.async.wait_group 0;" ::: "memory");
        __syncthreads();
        if (c + 3 < NC) load_stage(c + 3, (c + 3) & 3);

        uint32_t abase = sbase + (uint32_t)((c & 3) * STAGE_B);
        uint32_t wbase = abase + STGA_B;
        #pragma unroll
        for (int kc = 0; kc < 2; kc++) {
            uint32_t a[2][4], bfr[2][4];
            #pragma unroll
            for (int mt = 0; mt < 2; mt++)
                LDSM_X4(a[mt][0], a[mt][1], a[mt][2], a[mt][3],
                        abase + (uint32_t)((arow + mt * 16) * ROWG + acol + kc * 32));
            #pragma unroll
            for (int t = 0; t < 2; t++)
                LDSM_X4(bfr[t][0], bfr[t][1], bfr[t][2], bfr[t][3],
                        wbase + (uint32_t)((wrow + t * 16) * ROWG + wcol + kc * 32));
            #pragma unroll
            for (int mt = 0; mt < 2; mt++)
                #pragma unroll
                for (int t = 0; t < 2; t++) {
                    MMA_BF16(acc[mt][2 * t],     a[mt], bfr[t][0], bfr[t][1]);
                    MMA_BF16(acc[mt][2 * t + 1], a[mt], bfr[t][2], bfr[t][3]);
                }
        }
    }

    #pragma unroll
    for (int mt = 0; mt < 2; mt++) {
        #pragma unroll
        for (int nt = 0; nt < 4; nt++) {
            int cb = bn * 64 + wn * 32 + nt * 8 + 2 * qd;
            #pragma unroll
            for (int hi = 0; hi < 2; hi++) {
                int r = bm * 128 + wm * 32 + mt * 16 + g + hi * 8;
                float v0 = acc[mt][nt][hi * 2], v1 = acc[mt][nt][hi * 2 + 1];
                if (mode == MODE_QKV) {
                    int which = cb >> 9, h = (cb >> 6) & 7, d0 = cb & 63;
                    int bb = r >> 12, l = r & 4095;
                    __nv_bfloat16* dst = (which == 0) ? oq : (which == 1) ? okk : ov;
                    *(uint32_t*)(dst + (((size_t)bb * H_ + h) * L_ + l) * DH_ + d0) = packbf(v0, v1);
                } else if (mode == MODE_RESID) {
                    size_t idx = (size_t)r * N + cb;
                    float2 rv = *(const float2*)(resid + idx);
                    float2 o2 = {rv.x + v0, rv.y + v1};
                    *(float2*)(out + idx) = o2;
                } else {
                    size_t idx = (size_t)r * N + cb;
                    float a0s = v0 / (1.0f + __expf(-v0));
                    float a1s = v1 / (1.0f + __expf(-v1));
                    *(uint32_t*)(outb + idx) = packbf(a0s, a1s);
                }
            }
        }
    }
}

// ============ flash attention: 64-row Q, 128 thr, 4 CTA/SM ============
#define KSB 72
#define ROWB (KSB * 2)
#define OQ_B   0
#define OK_B   (64 * ROWB)
#define OV_B   (OK_B + 2 * 64 * ROWB)
#define OCB_B  (OV_B + 2 * 64 * ROWB)
#define ATTN_SMEM_B (OCB_B + 2 * 64 * 4)

__global__ __launch_bounds__(128, 4) void attn_kernel(
    const __nv_bfloat16* __restrict__ q, const __nv_bfloat16* __restrict__ k,
    const __nv_bfloat16* __restrict__ v, const float* __restrict__ ts,
    const float* __restrict__ mask, const float* __restrict__ decay_rate,
    __nv_bfloat16* __restrict__ out)
{
    extern __shared__ char smc[];
    uint32_t smb = (uint32_t)__cvta_generic_to_shared(smc);
    float* colb = (float*)(smc + OCB_B);

    int qt = gridDim.x - 1 - blockIdx.x;
    int bh = blockIdx.y, b = bh >> 3, h = bh & 7;
    int tid = threadIdx.x, wid = tid >> 5, lane = tid & 31;
    int g = lane >> 2, qd = lane & 3;
    int rbase = wid * 16;
    const int nkt = qt + 1;

    uint32_t qaddr = smb + OQ_B + (uint32_t)(rbase + (lane & 7) + ((lane >> 3) & 1) * 8) * ROWB
                   + (uint32_t)(lane >> 4) * 16;
    uint32_t kaddr = smb + OK_B + (uint32_t)((lane & 7) + ((lane >> 4) & 1) * 8) * ROWB
                   + (uint32_t)((lane >> 3) & 1) * 16;
    uint32_t vaddr = smb + OV_B + (uint32_t)((lane & 7) + ((lane >> 3) & 1) * 8) * ROWB
                   + (uint32_t)(lane >> 4) * 16;

    const __nv_bfloat16* qb = q + ((size_t)bh * L_ + qt * 64) * DH_;
    #pragma unroll
    for (int i = 0; i < 4; i++) {
        int idx = tid + i * 128;
        int r = idx >> 3, c8 = (idx & 7) << 3;
        *(uint4*)(smc + OQ_B + r * ROWB + c8 * 2) = *(const uint4*)(qb + (size_t)r * DH_ + c8);
    }

    const float LOG2E = 1.44269504f;
    float scale2 = 0.125f * LOG2E;
    float dcy2 = log1pf(__expf(decay_rate[h])) * (LOG2E / 24.0f);
    float mprev[2] = {-1e30f, -1e30f};
    float lsum[2] = {0.f, 0.f};
    float o[8][4];
    #pragma unroll
    for (int i = 0; i < 8; i++)
        #pragma unroll
        for (int e = 0; e < 4; e++) o[i][e] = 0.f;

    auto load_kv = [&](int jt, int st) {
        const __nv_bfloat16* kb = k + ((size_t)bh * L_ + jt * 64) * DH_;
        const __nv_bfloat16* vb = v + ((size_t)bh * L_ + jt * 64) * DH_;
        uint32_t kdst = smb + OK_B + (uint32_t)st * 64 * ROWB;
        uint32_t vdst = smb + OV_B + (uint32_t)st * 64 * ROWB;
        #pragma unroll
        for (int i = 0; i < 4; i++) {
            int idx = tid + i * 128;
            int r = idx >> 3, c8 = (idx & 7) << 3;
            asm volatile("cp.async.cg.shared.global [%0], [%1], 16;"
                         :: "r"(kdst + (uint32_t)(r * ROWB + c8 * 2)),
                            "l"(kb + (size_t)r * DH_ + c8) : "memory");
            asm volatile("cp.async.cg.shared.global [%0], [%1], 16;"
                         :: "r"(vdst + (uint32_t)(r * ROWB + c8 * 2)),
                            "l"(vb + (size_t)r * DH_ + c8) : "memory");
        }
        asm volatile("cp.async.commit_group;" ::: "memory");
        if (tid < 64) {
            float t = ts[b * L_ + jt * 64 + tid];
            float m = mask[b * L_ + jt * 64 + tid];
            colb[st * 64 + tid] = (m != 0.f) ? dcy2 * t : -3e38f;
        }
    };

    load_kv(0, 0);

    for (int jt = 0; jt < nkt; jt++) {
        int st = jt & 1;
        asm volatile("cp.async.wait_group 0;" ::: "memory");
        __syncthreads();
        if (jt + 1 < nkt) load_kv(jt + 1, (jt + 1) & 1);

        uint32_t kst = kaddr + (uint32_t)st * 64 * ROWB;
        uint32_t vst = vaddr + (uint32_t)st * 64 * ROWB;
        const float* cbs = colb + st * 64;
        bool diag = (jt == qt);

        float s[8][4];
        #pragma unroll
        for (int i = 0; i < 8; i++)
            #pragma unroll
            for (int e = 0; e < 4; e++) s[i][e] = 0.f;
        #pragma unroll
        for (int ks = 0; ks < 4; ks++) {
            uint32_t qa0, qa1, qa2, qa3;
            LDSM_X4(qa0, qa1, qa2, qa3, qaddr + ks * 32);
            uint32_t a[4] = {qa0, qa1, qa2, qa3};
            #pragma unroll
            for (int p = 0; p < 4; p++) {
                uint32_t b0, b1, b2, b3;
                LDSM_X4(b0, b1, b2, b3, kst + (uint32_t)(p * 16 * ROWB) + ks * 32);
                MMA_BF16(s[2 * p],     a, b0, b1);
                MMA_BF16(s[2 * p + 1], a, b2, b3);
            }
        }

        int qi0 = qt * 64 + rbase + g;
        #pragma unroll
        for (int nt = 0; nt < 8; nt++) {
            float2 cb2 = *(const float2*)(cbs + nt * 8 + 2 * qd);
            s[nt][0] = fmaf(s[nt][0], scale2, cb2.x);
            s[nt][1] = fmaf(s[nt][1], scale2, cb2.y);
            s[nt][2] = fmaf(s[nt][2], scale2, cb2.x);
            s[nt][3] = fmaf(s[nt][3], scale2, cb2.y);
            if (diag) {
                int colbase = jt * 64 + nt * 8 + 2 * qd;
                if (colbase     > qi0)     s[nt][0] = -3e38f;
                if (colbase + 1 > qi0)     s[nt][1] = -3e38f;
                if (colbase     > qi0 + 8) s[nt][2] = -3e38f;
                if (colbase + 1 > qi0 + 8) s[nt][3] = -3e38f;
            }
        }

        float rmax[2] = {-1e30f, -1e30f};
        #pragma unroll
        for (int nt = 0; nt < 8; nt++) {
            rmax[0] = fmaxf(rmax[0], fmaxf(s[nt][0], s[nt][1]));
            rmax[1] = fmaxf(rmax[1], fmaxf(s[nt][2], s[nt][3]));
        }
        #pragma unroll
        for (int off = 1; off < 4; off <<= 1) {
            rmax[0] = fmaxf(rmax[0], __shfl_xor_sync(0xffffffffu, rmax[0], off));
            rmax[1] = fmaxf(rmax[1], __shfl_xor_sync(0xffffffffu, rmax[1], off));
        }
        float mnew[2], fac[2];
        float psA[2] = {0.f, 0.f}, psB[2] = {0.f, 0.f};
        #pragma unroll
        for (int hi = 0; hi < 2; hi++) {
            mnew[hi] = fmaxf(mprev[hi], rmax[hi]);
            fac[hi]  = exp2fast(mprev[hi] - mnew[hi]);
        }
        #pragma unroll
        for (int nt = 0; nt < 8; nt++) {
            float p0 = exp2fast(s[nt][0] - mnew[0]);
            float p1 = exp2fast(s[nt][1] - mnew[0]);
            float p2 = exp2fast(s[nt][2] - mnew[1]);
            float p3 = exp2fast(s[nt][3] - mnew[1]);
            if (nt & 1) { psB[0] += p0 + p1; psB[1] += p2 + p3; }
            else        { psA[0] += p0 + p1; psA[1] += p2 + p3; }
            s[nt][0] = p0; s[nt][1] = p1; s[nt][2] = p2; s[nt][3] = p3;
        }
        float ps[2] = {psA[0] + psB[0], psA[1] + psB[1]};
        #pragma unroll
        for (int off = 1; off < 4; off <<= 1) {
            ps[0] += __shfl_xor_sync(0xffffffffu, ps[0], off);
            ps[1] += __shfl_xor_sync(0xffffffffu, ps[1], off);
        }
        #pragma unroll
        for (int hi = 0; hi < 2; hi++) {
            lsum[hi] = lsum[hi] * fac[hi] + ps[hi];
            mprev[hi] = mnew[hi];
        }
        #pragma unroll
        for (int nt = 0; nt < 8; nt++) {
            o[nt][0] *= fac[0]; o[nt][1] *= fac[0];
            o[nt][2] *= fac[1]; o[nt][3] *= fac[1];
        }

        #pragma unroll
        for (int kc = 0; kc < 4; kc++) {
            uint32_t a[4];
            a[0] = packbf(s[2 * kc][0],     s[2 * kc][1]);
            a[1] = packbf(s[2 * kc][2],     s[2 * kc][3]);
            a[2] = packbf(s[2 * kc + 1][0], s[2 * kc + 1][1]);
            a[3] = packbf(s[2 * kc + 1][2], s[2 * kc + 1][3]);
            #pragma unroll
            for (int p = 0; p < 4; p++) {
                uint32_t b0, b1, b2, b3;
                LDSM_X4T(b0, b1, b2, b3, vst + (uint32_t)(kc * 16 * ROWB) + p * 32);
                MMA_BF16(o[2 * p],     a, b0, b1);
                MMA_BF16(o[2 * p + 1], a, b2, b3);
            }
        }
    }

    float inv0 = 1.0f / lsum[0], inv1 = 1.0f / lsum[1];
    int r0 = qt * 64 + rbase + g;
    #pragma unroll
    for (int nt = 0; nt < 8; nt++) {
        int col = h * 64 + nt * 8 + 2 * qd;
        *(uint32_t*)(out + (size_t)(b * L_ + r0    ) * D_ + col) = packbf(o[nt][0] * inv0, o[nt][1] * inv0);
        *(uint32_t*)(out + (size_t)(b * L_ + r0 + 8) * D_ + col) = packbf(o[nt][2] * inv1, o[nt][3] * inv1);
    }
}

// ============ launch ============
extern "C" void kernel_launch(void* const* d_in, const int* in_sizes, int n_in,
                              void* d_out, int out_size) {
    const float* x     = (const float*)d_in[0];
    const float* tsb   = (const float*)d_in[1];
    const float* mask  = (const float*)d_in[2];
    const float* ln1_g = (const float*)d_in[3];
    const float* ln1_b = (const float*)d_in[4];
    const float* w_qkv = (const float*)d_in[5];
    const float* w_out = (const float*)d_in[6];
    const float* decay = (const float*)d_in[7];
    const float* ln2_g = (const float*)d_in[8];
    const float* ln2_b = (const float*)d_in[9];
    const float* w_ff1 = (const float*)d_in[10];
    const float* w_ff2 = (const float*)d_in[11];
    float* out = (float*)d_out;

    __nv_bfloat16 *xn, *q, *k, *v, *att, *hh, *ff, *w0, *w1, *w2, *w3;
    float *x1;
    cudaGetSymbolAddress((void**)&xn, g_xn);
    cudaGetSymbolAddress((void**)&q, g_q);
    cudaGetSymbolAddress((void**)&k, g_k);
    cudaGetSymbolAddress((void**)&v, g_v);
    cudaGetSymbolAddress((void**)&att, g_att);
    cudaGetSymbolAddress((void**)&x1, g_x1);
    cudaGetSymbolAddress((void**)&hh, g_h);
    cudaGetSymbolAddress((void**)&ff, g_ff);
    cudaGetSymbolAddress((void**)&w0, g_w0);
    cudaGetSymbolAddress((void**)&w1, g_w1);
    cudaGetSymbolAddress((void**)&w2, g_w2);
    cudaGetSymbolAddress((void**)&w3, g_w3);

    cudaFuncSetAttribute(mma_gemm, cudaFuncAttributeMaxDynamicSharedMemorySize, GEMM_SMEM_B);
    cudaFuncSetAttribute(attn_kernel, cudaFuncAttributeMaxDynamicSharedMemorySize, ATTN_SMEM_B);

    prep_kernel<<<NW_BLOCKS + BL_, 256>>>(w_qkv, w0, w_out, w1, w_ff1, w2, w_ff2, w3,
                                          x, ln1_g, ln1_b, xn);
    mma_gemm<<<dim3(1536 / 64, BL_ / 128), 256, GEMM_SMEM_B>>>(
        xn, w0, D_, 1536, MODE_QKV, nullptr, nullptr, nullptr, q, k, v);
    attn_kernel<<<dim3(L_ / 64, B_ * H_), 128, ATTN_SMEM_B>>>(
        q, k, v, tsb, mask, decay, att);
    mma_gemm<<<dim3(D_ / 64, BL_ / 128), 256, GEMM_SMEM_B>>>(
        att, w1, D_, D_, MODE_RESID, x, x1, nullptr, nullptr, nullptr, nullptr);
    ln_kernel<<<BL_, 256>>>(x1, ln2_g, ln2_b, hh);
    mma_gemm<<<dim3(FF_ / 64, BL_ / 128), 256, GEMM_SMEM_B>>>(
        hh, w2, D_, FF_, MODE_SILU, nullptr, nullptr, ff, nullptr, nullptr, nullptr);
    mma_gemm<<<dim3(D_ / 64, BL_ / 128), 256, GEMM_SMEM_B>>>(
        ff, w3, FF_, D_, MODE_RESID, x1, out, nullptr, nullptr, nullptr, nullptr);
}

// round 15
// speedup vs baseline: 1.1073x; 1.1073x over previous
#include <cuda_runtime.h>
#include <cuda_bf16.h>
#include <math.h>
#include <stdint.h>

#define B_  2
#define L_  4096
#define D_  512
#define H_  8
#define DH_ 64
#define BL_ 8192
#define FF_ 2048

// ---------------- scratch ----------------
__device__ __nv_bfloat16 g_xn [BL_ * D_];
__device__ __nv_bfloat16 g_q [B_ * H_ * L_ * DH_];
__device__ __nv_bfloat16 g_k [B_ * H_ * L_ * DH_];
__device__ __nv_bfloat16 g_v [B_ * H_ * L_ * DH_];
__device__ __nv_bfloat16 g_att[BL_ * D_];
__device__ float g_x1 [BL_ * D_];
__device__ __nv_bfloat16 g_h  [BL_ * D_];
__device__ __nv_bfloat16 g_ff [BL_ * FF_];
__device__ __nv_bfloat16 g_w0 [3 * D_ * D_];
__device__ __nv_bfloat16 g_w1 [D_ * D_];
__device__ __nv_bfloat16 g_w2 [FF_ * D_];
__device__ __nv_bfloat16 g_w3 [D_ * FF_];

__device__ __forceinline__ float exp2fast(float x) {
    float r;
    asm("ex2.approx.f32 %0, %1;" : "=f"(r) : "f"(x));
    return r;
}
__device__ __forceinline__ uint32_t packbf(float lo, float hi) {
    uint32_t r;
    asm("cvt.rn.bf16x2.f32 %0, %1, %2;" : "=r"(r) : "f"(hi), "f"(lo));
    return r;
}

#define MMA_BF16(d, a, b0, b1)                                               \
    asm volatile(                                                            \
        "mma.sync.aligned.m16n8k16.row.col.f32.bf16.bf16.f32 "               \
        "{%0,%1,%2,%3}, {%4,%5,%6,%7}, {%8,%9}, {%0,%1,%2,%3};"              \
        : "+f"(d[0]), "+f"(d[1]), "+f"(d[2]), "+f"(d[3])                     \
        : "r"(a[0]), "r"(a[1]), "r"(a[2]), "r"(a[3]), "r"(b0), "r"(b1))

#define LDSM_X4(r0, r1, r2, r3, addr)                                        \
    asm volatile("ldmatrix.sync.aligned.m8n8.x4.shared.b16 {%0,%1,%2,%3}, [%4];" \
        : "=r"(r0), "=r"(r1), "=r"(r2), "=r"(r3) : "r"(addr))

#define LDSM_X4T(r0, r1, r2, r3, addr)                                       \
    asm volatile("ldmatrix.sync.aligned.m8n8.x4.trans.shared.b16 {%0,%1,%2,%3}, [%4];" \
        : "=r"(r0), "=r"(r1), "=r"(r2), "=r"(r3) : "r"(addr))

// ============ fused prep: weight conversion + LN1 ============
#define NW_BLOCKS ((3 * D_ * D_ + D_ * D_ + FF_ * D_ + D_ * FF_) / 1024)

__global__ __launch_bounds__(256) void prep_kernel(
    const float* __restrict__ s0, __nv_bfloat16* __restrict__ d0,
    const float* __restrict__ s1, __nv_bfloat16* __restrict__ d1,
    const float* __restrict__ s2, __nv_bfloat16* __restrict__ d2,
    const float* __restrict__ s3, __nv_bfloat16* __restrict__ d3,
    const float* __restrict__ x, const float* __restrict__ lg,
    const float* __restrict__ lb, __nv_bfloat16* __restrict__ y)
{
    if (blockIdx.x < NW_BLOCKS) {
        const int n0 = 3 * D_ * D_, n1 = D_ * D_, n2 = FF_ * D_;
        int i = (blockIdx.x * 256 + threadIdx.x) * 4;
        const float* src; __nv_bfloat16* dst; int off;
        if (i < n0)                { src = s0; dst = d0; off = i; }
        else if (i < n0 + n1)      { src = s1; dst = d1; off = i - n0; }
        else if (i < n0 + n1 + n2) { src = s2; dst = d2; off = i - n0 - n1; }
        else                       { src = s3; dst = d3; off = i - n0 - n1 - n2; }
        float4 v = *(const float4*)(src + off);
        uint2 o;
        o.x = packbf(v.x, v.y);
        o.y = packbf(v.z, v.w);
        *(uint2*)(dst + off) = o;
        return;
    }
    int row = blockIdx.x - NW_BLOCKS;
    const float* xr = x + (size_t)row * D_;
    __nv_bfloat16* yr = y + (size_t)row * D_;
    int tid = threadIdx.x;
    float v0 = xr[tid], v1 = xr[tid + 256];
    float s = v0 + v1, ss = v0 * v0 + v1 * v1;
    #pragma unroll
    for (int o = 16; o > 0; o >>= 1) {
        s  += __shfl_xor_sync(0xffffffffu, s,  o);
        ss += __shfl_xor_sync(0xffffffffu, ss, o);
    }
    __shared__ float red[16];
    int w = tid >> 5, lane = tid & 31;
    if (lane == 0) { red[w] = s; red[w + 8] = ss; }
    __syncthreads();
    float S = 0.f, SS = 0.f;
    #pragma unroll
    for (int i = 0; i < 8; i++) { S += red[i]; SS += red[i + 8]; }
    float mu = S * (1.0f / D_);
    float inv = rsqrtf(SS * (1.0f / D_) - mu * mu + 1e-5f);
    yr[tid]       = __float2bfloat16((v0 - mu) * inv * lg[tid]       + lb[tid]);
    yr[tid + 256] = __float2bfloat16((v1 - mu) * inv * lg[tid + 256] + lb[tid + 256]);
}

// ============ LayerNorm (standalone, for LN2) ============
__global__ __launch_bounds__(256) void ln_kernel(const float* __restrict__ x,
                                                 const float* __restrict__ g,
                                                 const float* __restrict__ b,
                                                 __nv_bfloat16* __restrict__ y) {
    int row = blockIdx.x;
    const float* xr = x + (size_t)row * D_;
    __nv_bfloat16* yr = y + (size_t)row * D_;
    int tid = threadIdx.x;
    float v0 = xr[tid], v1 = xr[tid + 256];
    float s = v0 + v1, ss = v0 * v0 + v1 * v1;
    #pragma unroll
    for (int o = 16; o > 0; o >>= 1) {
        s  += __shfl_xor_sync(0xffffffffu, s,  o);
        ss += __shfl_xor_sync(0xffffffffu, ss, o);
    }
    __shared__ float red[16];
    int w = tid >> 5, lane = tid & 31;
    if (lane == 0) { red[w] = s; red[w + 8] = ss; }
    __syncthreads();
    float S = 0.f, SS = 0.f;
    #pragma unroll
    for (int i = 0; i < 8; i++) { S += red[i]; SS += red[i + 8]; }
    float mu = S * (1.0f / D_);
    float inv = rsqrtf(SS * (1.0f / D_) - mu * mu + 1e-5f);
    yr[tid]       = __float2bfloat16((v0 - mu) * inv * g[tid]       + b[tid]);
    yr[tid + 256] = __float2bfloat16((v1 - mu) * inv * g[tid + 256] + b[tid + 256]);
}

// ============ bf16 mma GEMM: 128x128 block, 2(M)x4(N) warps, 64x32 warp tile,
//              K-chunk 64, 3-stage cp.async, 2 CTA/SM ============
#define ROWG 144                         // bytes per smem row (64 bf16 + 8 pad)
#define STG_B (128 * ROWG)               // 18432 per matrix
#define STAGE_B (2 * STG_B)              // 36864
#define GEMM_SMEM_B (3 * STAGE_B)        // 110592
#define MODE_QKV   0
#define MODE_RESID 1
#define MODE_SILU  2

__global__ __launch_bounds__(256, 2) void mma_gemm(
    const __nv_bfloat16* __restrict__ A, const __nv_bfloat16* __restrict__ W,
    int K, int N, int mode, const float* __restrict__ resid,
    float* __restrict__ out, __nv_bfloat16* __restrict__ outb,
    __nv_bfloat16* __restrict__ oq, __nv_bfloat16* __restrict__ okk,
    __nv_bfloat16* __restrict__ ov)
{
    extern __shared__ char smg[];
    uint32_t sbase = (uint32_t)__cvta_generic_to_shared(smg);
    int tid = threadIdx.x;
    int wid = tid >> 5, lane = tid & 31;
    int wm = wid & 1, wn = wid >> 1;
    int g = lane >> 2, qd = lane & 3;
    int bm = blockIdx.y, bn = blockIdx.x;
    const __nv_bfloat16* Ab = A + (size_t)bm * 128 * K;
    const __nv_bfloat16* Wb = W + (size_t)bn * 128 * K;
    const int NC = K >> 6;               // K-chunk 64

    int arow = wm * 64 + (lane & 7) + ((lane >> 3) & 1) * 8;
    int acol = (lane >> 4) * 16;
    int wrow = wn * 32 + (lane & 7) + ((lane >> 4) & 1) * 8;
    int wcol = ((lane >> 3) & 1) * 16;

    float acc[4][4][4];
    #pragma unroll
    for (int i = 0; i < 4; i++)
        #pragma unroll
        for (int j = 0; j < 4; j++)
            #pragma unroll
            for (int e = 0; e < 4; e++) acc[i][j][e] = 0.f;

    auto load_stage = [&](int c, int st) {
        int k0 = c << 6;
        #pragma unroll
        for (int i = 0; i < 4; i++) {
            int idx = tid + i * 256;
            int r = idx >> 3, cb = idx & 7;
            uint32_t da = sbase + (uint32_t)(st * STAGE_B + r * ROWG + cb * 16);
            asm volatile("cp.async.cg.shared.global [%0], [%1], 16;"
                         :: "r"(da), "l"(Ab + (size_t)r * K + k0 + cb * 8) : "memory");
            asm volatile("cp.async.cg.shared.global [%0], [%1], 16;"
                         :: "r"(da + STG_B), "l"(Wb + (size_t)r * K + k0 + cb * 8) : "memory");
        }
        asm volatile("cp.async.commit_group;" ::: "memory");
    };

    load_stage(0, 0);
    if (NC > 1) load_stage(1, 1);
    int st = 0, stn = (NC > 1) ? 2 : 1;

    for (int c = 0; c < NC; c++) {
        if (c + 1 < NC) asm volatile("cp.async.wait_group 1;" ::: "memory");
        else            asm volatile("cp.async.wait_group 0;" ::: "memory");
        __syncthreads();                   // publish chunk c; all done reading old slot
        if (c + 2 < NC) {
            load_stage(c + 2, stn);
            stn = (stn == 2) ? 0 : stn + 1;
        }

        uint32_t abase = sbase + (uint32_t)(st * STAGE_B);
        uint32_t wbase = abase + STG_B;
        #pragma unroll
        for (int kc = 0; kc < 4; kc++) {
            uint32_t a[4][4], bfr[2][4];
            #pragma unroll
            for (int mt = 0; mt < 4; mt++)
                LDSM_X4(a[mt][0], a[mt][1], a[mt][2], a[mt][3],
                        abase + (uint32_t)((arow + mt * 16) * ROWG + acol + kc * 32));
            #pragma unroll
            for (int t = 0; t < 2; t++)
                LDSM_X4(bfr[t][0], bfr[t][1], bfr[t][2], bfr[t][3],
                        wbase + (uint32_t)((wrow + t * 16) * ROWG + wcol + kc * 32));
            #pragma unroll
            for (int mt = 0; mt < 4; mt++)
                #pragma unroll
                for (int t = 0; t < 2; t++) {
                    MMA_BF16(acc[mt][2 * t],     a[mt], bfr[t][0], bfr[t][1]);
                    MMA_BF16(acc[mt][2 * t + 1], a[mt], bfr[t][2], bfr[t][3]);
                }
        }
        st = (st == 2) ? 0 : st + 1;
    }

    #pragma unroll
    for (int mt = 0; mt < 4; mt++) {
        #pragma unroll
        for (int nt = 0; nt < 4; nt++) {
            int cb = bn * 128 + wn * 32 + nt * 8 + 2 * qd;
            #pragma unroll
            for (int hi = 0; hi < 2; hi++) {
                int r = bm * 128 + wm * 64 + mt * 16 + g + hi * 8;
                float v0 = acc[mt][nt][hi * 2], v1 = acc[mt][nt][hi * 2 + 1];
                if (mode == MODE_QKV) {
                    int which = cb >> 9, h = (cb >> 6) & 7, d0 = cb & 63;
                    int bb = r >> 12, l = r & 4095;
                    __nv_bfloat16* dst = (which == 0) ? oq : (which == 1) ? okk : ov;
                    *(uint32_t*)(dst + (((size_t)bb * H_ + h) * L_ + l) * DH_ + d0) = packbf(v0, v1);
                } else if (mode == MODE_RESID) {
                    size_t idx = (size_t)r * N + cb;
                    float2 rv = *(const float2*)(resid + idx);
                    float2 o2 = {rv.x + v0, rv.y + v1};
                    *(float2*)(out + idx) = o2;
                } else {
                    size_t idx = (size_t)r * N + cb;
                    float a0s = v0 / (1.0f + __expf(-v0));
                    float a1s = v1 / (1.0f + __expf(-v1));
                    *(uint32_t*)(outb + idx) = packbf(a0s, a1s);
                }
            }
        }
    }
}

// ============ flash attention: 64-row Q, 128 thr, 4 CTA/SM (R13 state) ============
#define KSB 72
#define ROWB (KSB * 2)
#define OQ_B   0
#define OK_B   (64 * ROWB)
#define OV_B   (OK_B + 2 * 64 * ROWB)
#define OCB_B  (OV_B + 2 * 64 * ROWB)
#define ATTN_SMEM_B (OCB_B + 2 * 64 * 4)

__global__ __launch_bounds__(128, 4) void attn_kernel(
    const __nv_bfloat16* __restrict__ q, const __nv_bfloat16* __restrict__ k,
    const __nv_bfloat16* __restrict__ v, const float* __restrict__ ts,
    const float* __restrict__ mask, const float* __restrict__ decay_rate,
    __nv_bfloat16* __restrict__ out)
{
    extern __shared__ char smc[];
    uint32_t smb = (uint32_t)__cvta_generic_to_shared(smc);
    float* colb = (float*)(smc + OCB_B);

    int qt = gridDim.x - 1 - blockIdx.x;
    int bh = blockIdx.y, b = bh >> 3, h = bh & 7;
    int tid = threadIdx.x, wid = tid >> 5, lane = tid & 31;
    int g = lane >> 2, qd = lane & 3;
    int rbase = wid * 16;
    const int nkt = qt + 1;

    uint32_t qaddr = smb + OQ_B + (uint32_t)(rbase + (lane & 7) + ((lane >> 3) & 1) * 8) * ROWB
                   + (uint32_t)(lane >> 4) * 16;
    uint32_t kaddr = smb + OK_B + (uint32_t)((lane & 7) + ((lane >> 4) & 1) * 8) * ROWB
                   + (uint32_t)((lane >> 3) & 1) * 16;
    uint32_t vaddr = smb + OV_B + (uint32_t)((lane & 7) + ((lane >> 3) & 1) * 8) * ROWB
                   + (uint32_t)(lane >> 4) * 16;

    const __nv_bfloat16* qb = q + ((size_t)bh * L_ + qt * 64) * DH_;
    #pragma unroll
    for (int i = 0; i < 4; i++) {
        int idx = tid + i * 128;
        int r = idx >> 3, c8 = (idx & 7) << 3;
        *(uint4*)(smc + OQ_B + r * ROWB + c8 * 2) = *(const uint4*)(qb + (size_t)r * DH_ + c8);
    }

    const float LOG2E = 1.44269504f;
    float scale2 = 0.125f * LOG2E;
    float dcy2 = log1pf(__expf(decay_rate[h])) * (LOG2E / 24.0f);
    float mprev[2] = {-1e30f, -1e30f};
    float lsum[2] = {0.f, 0.f};
    float o[8][4];
    #pragma unroll
    for (int i = 0; i < 8; i++)
        #pragma unroll
        for (int e = 0; e < 4; e++) o[i][e] = 0.f;

    auto load_kv = [&](int jt, int st) {
        const __nv_bfloat16* kb = k + ((size_t)bh * L_ + jt * 64) * DH_;
        const __nv_bfloat16* vb = v + ((size_t)bh * L_ + jt * 64) * DH_;
        uint32_t kdst = smb + OK_B + (uint32_t)st * 64 * ROWB;
        uint32_t vdst = smb + OV_B + (uint32_t)st * 64 * ROWB;
        #pragma unroll
        for (int i = 0; i < 4; i++) {
            int idx = tid + i * 128;
            int r = idx >> 3, c8 = (idx & 7) << 3;
            asm volatile("cp.async.cg.shared.global [%0], [%1], 16;"
                         :: "r"(kdst + (uint32_t)(r * ROWB + c8 * 2)),
                            "l"(kb + (size_t)r * DH_ + c8) : "memory");
            asm volatile("cp.async.cg.shared.global [%0], [%1], 16;"
                         :: "r"(vdst + (uint32_t)(r * ROWB + c8 * 2)),
                            "l"(vb + (size_t)r * DH_ + c8) : "memory");
        }
        asm volatile("cp.async.commit_group;" ::: "memory");
        if (tid < 64) {
            float t = ts[b * L_ + jt * 64 + tid];
            float m = mask[b * L_ + jt * 64 + tid];
            colb[st * 64 + tid] = (m != 0.f) ? dcy2 * t : -3e38f;
        }
    };

    load_kv(0, 0);

    for (int jt = 0; jt < nkt; jt++) {
        int st = jt & 1;
        asm volatile("cp.async.wait_group 0;" ::: "memory");
        __syncthreads();
        if (jt + 1 < nkt) load_kv(jt + 1, (jt + 1) & 1);

        uint32_t kst = kaddr + (uint32_t)st * 64 * ROWB;
        uint32_t vst = vaddr + (uint32_t)st * 64 * ROWB;
        const float* cbs = colb + st * 64;
        bool diag = (jt == qt);

        float s[8][4];
        #pragma unroll
        for (int i = 0; i < 8; i++)
            #pragma unroll
            for (int e = 0; e < 4; e++) s[i][e] = 0.f;
        #pragma unroll
        for (int ks = 0; ks < 4; ks++) {
            uint32_t qa0, qa1, qa2, qa3;
            LDSM_X4(qa0, qa1, qa2, qa3, qaddr + ks * 32);
            uint32_t a[4] = {qa0, qa1, qa2, qa3};
            #pragma unroll
            for (int p = 0; p < 4; p++) {
                uint32_t b0, b1, b2, b3;
                LDSM_X4(b0, b1, b2, b3, kst + (uint32_t)(p * 16 * ROWB) + ks * 32);
                MMA_BF16(s[2 * p],     a, b0, b1);
                MMA_BF16(s[2 * p + 1], a, b2, b3);
            }
        }

        int qi0 = qt * 64 + rbase + g;
        #pragma unroll
        for (int nt = 0; nt < 8; nt++) {
            float2 cb2 = *(const float2*)(cbs + nt * 8 + 2 * qd);
            s[nt][0] = fmaf(s[nt][0], scale2, cb2.x);
            s[nt][1] = fmaf(s[nt][1], scale2, cb2.y);
            s[nt][2] = fmaf(s[nt][2], scale2, cb2.x);
            s[nt][3] = fmaf(s[nt][3], scale2, cb2.y);
            if (diag) {
                int colbase = jt * 64 + nt * 8 + 2 * qd;
                if (colbase     > qi0)     s[nt][0] = -3e38f;
                if (colbase + 1 > qi0)     s[nt][1] = -3e38f;
                if (colbase     > qi0 + 8) s[nt][2] = -3e38f;
                if (colbase + 1 > qi0 + 8) s[nt][3] = -3e38f;
            }
        }

        float rmax[2] = {-1e30f, -1e30f};
        #pragma unroll
        for (int nt = 0; nt < 8; nt++) {
            rmax[0] = fmaxf(rmax[0], fmaxf(s[nt][0], s[nt][1]));
            rmax[1] = fmaxf(rmax[1], fmaxf(s[nt][2], s[nt][3]));
        }
        #pragma unroll
        for (int off = 1; off < 4; off <<= 1) {
            rmax[0] = fmaxf(rmax[0], __shfl_xor_sync(0xffffffffu, rmax[0], off));
            rmax[1] = fmaxf(rmax[1], __shfl_xor_sync(0xffffffffu, rmax[1], off));
        }
        float mnew[2], fac[2];
        float psA[2] = {0.f, 0.f}, psB[2] = {0.f, 0.f};
        #pragma unroll
        for (int hi = 0; hi < 2; hi++) {
            mnew[hi] = fmaxf(mprev[hi], rmax[hi]);
            fac[hi]  = exp2fast(mprev[hi] - mnew[hi]);
        }
        #pragma unroll
        for (int nt = 0; nt < 8; nt++) {
            float p0 = exp2fast(s[nt][0] - mnew[0]);
            float p1 = exp2fast(s[nt][1] - mnew[0]);
            float p2 = exp2fast(s[nt][2] - mnew[1]);
            float p3 = exp2fast(s[nt][3] - mnew[1]);
            if (nt & 1) { psB[0] += p0 + p1; psB[1] += p2 + p3; }
            else        { psA[0] += p0 + p1; psA[1] += p2 + p3; }
            s[nt][0] = p0; s[nt][1] = p1; s[nt][2] = p2; s[nt][3] = p3;
        }
        float ps[2] = {psA[0] + psB[0], psA[1] + psB[1]};
        #pragma unroll
        for (int off = 1; off < 4; off <<= 1) {
            ps[0] += __shfl_xor_sync(0xffffffffu, ps[0], off);
            ps[1] += __shfl_xor_sync(0xffffffffu, ps[1], off);
        }
        #pragma unroll
        for (int hi = 0; hi < 2; hi++) {
            lsum[hi] = lsum[hi] * fac[hi] + ps[hi];
            mprev[hi] = mnew[hi];
        }
        #pragma unroll
        for (int nt = 0; nt < 8; nt++) {
            o[nt][0] *= fac[0]; o[nt][1] *= fac[0];
            o[nt][2] *= fac[1]; o[nt][3] *= fac[1];
        }

        #pragma unroll
        for (int kc = 0; kc < 4; kc++) {
            uint32_t a[4];
            a[0] = packbf(s[2 * kc][0],     s[2 * kc][1]);
            a[1] = packbf(s[2 * kc][2],     s[2 * kc][3]);
            a[2] = packbf(s[2 * kc + 1][0], s[2 * kc + 1][1]);
            a[3] = packbf(s[2 * kc + 1][2], s[2 * kc + 1][3]);
            #pragma unroll
            for (int p = 0; p < 4; p++) {
                uint32_t b0, b1, b2, b3;
                LDSM_X4T(b0, b1, b2, b3, vst + (uint32_t)(kc * 16 * ROWB) + p * 32);
                MMA_BF16(o[2 * p],     a, b0, b1);
                MMA_BF16(o[2 * p + 1], a, b2, b3);
            }
        }
    }

    float inv0 = 1.0f / lsum[0], inv1 = 1.0f / lsum[1];
    int r0 = qt * 64 + rbase + g;
    #pragma unroll
    for (int nt = 0; nt < 8; nt++) {
        int col = h * 64 + nt * 8 + 2 * qd;
        *(uint32_t*)(out + (size_t)(b * L_ + r0    ) * D_ + col) = packbf(o[nt][0] * inv0, o[nt][1] * inv0);
        *(uint32_t*)(out + (size_t)(b * L_ + r0 + 8) * D_ + col) = packbf(o[nt][2] * inv1, o[nt][3] * inv1);
    }
}

// ============ launch ============
extern "C" void kernel_launch(void* const* d_in, const int* in_sizes, int n_in,
                              void* d_out, int out_size) {
    const float* x     = (const float*)d_in[0];
    const float* tsb   = (const float*)d_in[1];
    const float* mask  = (const float*)d_in[2];
    const float* ln1_g = (const float*)d_in[3];
    const float* ln1_b = (const float*)d_in[4];
    const float* w_qkv = (const float*)d_in[5];
    const float* w_out = (const float*)d_in[6];
    const float* decay = (const float*)d_in[7];
    const float* ln2_g = (const float*)d_in[8];
    const float* ln2_b = (const float*)d_in[9];
    const float* w_ff1 = (const float*)d_in[10];
    const float* w_ff2 = (const float*)d_in[11];
    float* out = (float*)d_out;

    __nv_bfloat16 *xn, *q, *k, *v, *att, *hh, *ff, *w0, *w1, *w2, *w3;
    float *x1;
    cudaGetSymbolAddress((void**)&xn, g_xn);
    cudaGetSymbolAddress((void**)&q, g_q);
    cudaGetSymbolAddress((void**)&k, g_k);
    cudaGetSymbolAddress((void**)&v, g_v);
    cudaGetSymbolAddress((void**)&att, g_att);
    cudaGetSymbolAddress((void**)&x1, g_x1);
    cudaGetSymbolAddress((void**)&hh, g_h);
    cudaGetSymbolAddress((void**)&ff, g_ff);
    cudaGetSymbolAddress((void**)&w0, g_w0);
    cudaGetSymbolAddress((void**)&w1, g_w1);
    cudaGetSymbolAddress((void**)&w2, g_w2);
    cudaGetSymbolAddress((void**)&w3, g_w3);

    cudaFuncSetAttribute(mma_gemm, cudaFuncAttributeMaxDynamicSharedMemorySize, GEMM_SMEM_B);
    cudaFuncSetAttribute(attn_kernel, cudaFuncAttributeMaxDynamicSharedMemorySize, ATTN_SMEM_B);

    prep_kernel<<<NW_BLOCKS + BL_, 256>>>(w_qkv, w0, w_out, w1, w_ff1, w2, w_ff2, w3,
                                          x, ln1_g, ln1_b, xn);
    mma_gemm<<<dim3(1536 / 128, BL_ / 128), 256, GEMM_SMEM_B>>>(
        xn, w0, D_, 1536, MODE_QKV, nullptr, nullptr, nullptr, q, k, v);
    attn_kernel<<<dim3(L_ / 64, B_ * H_), 128, ATTN_SMEM_B>>>(
        q, k, v, tsb, mask, decay, att);
    mma_gemm<<<dim3(D_ / 128, BL_ / 128), 256, GEMM_SMEM_B>>>(
        att, w1, D_, D_, MODE_RESID, x, x1, nullptr, nullptr, nullptr, nullptr);
    ln_kernel<<<BL_, 256>>>(x1, ln2_g, ln2_b, hh);
    mma_gemm<<<dim3(FF_ / 128, BL_ / 128), 256, GEMM_SMEM_B>>>(
        hh, w2, D_, FF_, MODE_SILU, nullptr, nullptr, ff, nullptr, nullptr, nullptr);
    mma_gemm<<<dim3(D_ / 128, BL_ / 128), 256, GEMM_SMEM_B>>>(
        ff, w3, FF_, D_, MODE_RESID, x1, out, nullptr, nullptr, nullptr, nullptr);
}